// round 13
// baseline (speedup 1.0000x reference)
#include <cuda_runtime.h>
#include <cstdint>

// HighOrderFactorizationMachineModel: BATCH=16384, F=20 fields (dim 50000 each),
// EMBED_DIM=16, ORDER=3. emb_table row = 32 floats: [0:16) order-2 dims,
// [16:32) order-3 dims. Closed forms via power sums (Newton identities):
//   e2 = (p1^2 - p2)/2
//   e3 = (p1^3 - 3 p1 p2 + 2 p3)/6
// collapsing the O(F^2 D) ANOVA DP to 3 accumulators per dim.
//
// FINAL (R13 = R1, the thrice-validated 10.7us optimum, minus dead guard,
// plus streaming output store).
// Twelve rounds of evidence: pinned at the random-gather roofline.
//   cold:  41MB compulsory unique lines @ ~3.3TB/s random-HBM ceiling
//   warm:  ~655k miss-requests through the ~66-outstanding-lines/SM L1tex
//          pool at ~250cyc L2 latency
// Request count is minimal (40 random lines/sample, nothing coalescable).
// Structure-invariant across MLP 4..20, occ 39..109%, LDG.32/.128; all
// alternative load paths (cp.async.cg, L2 cache hints both polarities,
// cp.async.bulk) and the emb-before-lin reorder regressed 40-60%.
// Load ordering is load-bearing: the divergent lin gather issues EARLY so
// its 20 scattered-sector wavefronts overlap the emb line fills instead of
// queuing behind the next warps' batches (R11: violating this costs 40%).

#define FM_BATCH 16384
#define FM_F 20
#define FM_FIELD_DIM 50000

__global__ __launch_bounds__(256)
void fm_ho_kernel(const int* __restrict__ x,
                  const float* __restrict__ emb,
                  const float* __restrict__ lin,
                  const float* __restrict__ bias,
                  float* __restrict__ out)
{
    const int warp = (blockIdx.x * blockDim.x + threadIdx.x) >> 5;
    const int lane = threadIdx.x & 31;

    // Lane f holds the global table index for field f (offsets = f * 50000).
    // The lin gather issues here, FIRST, overlapping all emb line fills.
    int gidx = 0;
    float linv = 0.0f;
    if (lane < FM_F) {
        gidx = x[warp * FM_F + lane] + lane * FM_FIELD_DIM;
        linv = __ldg(&lin[gidx]);
    }

    float p1 = 0.0f, p2 = 0.0f, p3 = 0.0f;

    #pragma unroll
    for (int f = 0; f < FM_F; f++) {
        const int idx = __shfl_sync(0xffffffffu, gidx, f);
        const float v = __ldg(&emb[(long)idx * 32 + lane]);
        const float v2 = v * v;
        p1 += v;
        p2 += v2;
        p3 += v2 * v;
    }

    // Lanes 0..15: order-2 dims. Lanes 16..31: order-3 dims.
    float term;
    if (lane < 16) {
        term = 0.5f * (p1 * p1 - p2);
    } else {
        term = (p1 * p1 * p1 - 3.0f * p1 * p2 + 2.0f * p3) * (1.0f / 6.0f);
    }
    term += linv;  // lanes 0..19 contribute linear part, others added 0

    // Warp-wide sum.
    #pragma unroll
    for (int o = 16; o > 0; o >>= 1)
        term += __shfl_xor_sync(0xffffffffu, term, o);

    // Streaming store: output has zero reuse; keep it out of L2's way.
    if (lane == 0)
        __stcs(&out[warp], term + __ldg(&bias[0]));
}

extern "C" void kernel_launch(void* const* d_in, const int* in_sizes, int n_in,
                              void* d_out, int out_size)
{
    const int*   x    = (const int*)d_in[0];
    const float* emb  = (const float*)d_in[1];
    const float* lin  = (const float*)d_in[2];
    const float* bias = (const float*)d_in[3];
    float*       out  = (float*)d_out;

    // 16384 samples, 1 warp each, 8 warps/block -> 2048 blocks (exact grid).
    const int threads = 256;
    const int blocks  = (FM_BATCH * 32) / threads;
    fm_ho_kernel<<<blocks, threads>>>(x, emb, lin, bias, out);
}

// round 14
// speedup vs baseline: 1.0060x; 1.0060x over previous
#include <cuda_runtime.h>
#include <cstdint>

// HighOrderFactorizationMachineModel: BATCH=16384, F=20 fields (dim 50000 each),
// EMBED_DIM=16, ORDER=3. emb_table row = 32 floats: [0:16) order-2 dims,
// [16:32) order-3 dims. Closed forms via power sums (Newton identities):
//   e2 = (p1^2 - p2)/2
//   e3 = (p1^3 - 3 p1 p2 + 2 p3)/6
// collapsing the O(F^2 D) ANOVA DP to 3 accumulators per dim.
//
// R14 = R13 skeleton (thrice-validated 10.7us fixed point) with ONE change:
// gathers use __ldcg (LDG.E.CG, L2-only, no L1 allocation). Every gathered
// line is touched once (random addresses, 279k unique rows >> 228KB L1), so
// L1 allocation is pure overhead; .CG skips it with no per-thread policy
// operand (unlike the cache-hint forms that regressed 40% in R8/R9).
// Load ordering preserved exactly: divergent lin gather issues FIRST,
// overlapping the emb line fills (R11: violating this costs 40%).

#define FM_BATCH 16384
#define FM_F 20
#define FM_FIELD_DIM 50000

__global__ __launch_bounds__(256)
void fm_ho_kernel(const int* __restrict__ x,
                  const float* __restrict__ emb,
                  const float* __restrict__ lin,
                  const float* __restrict__ bias,
                  float* __restrict__ out)
{
    const int warp = (blockIdx.x * blockDim.x + threadIdx.x) >> 5;
    const int lane = threadIdx.x & 31;

    // Lane f holds the global table index for field f (offsets = f * 50000).
    // The lin gather issues here, FIRST, overlapping all emb line fills.
    int gidx = 0;
    float linv = 0.0f;
    if (lane < FM_F) {
        gidx = x[warp * FM_F + lane] + lane * FM_FIELD_DIM;
        linv = __ldcg(&lin[gidx]);
    }

    float p1 = 0.0f, p2 = 0.0f, p3 = 0.0f;

    #pragma unroll
    for (int f = 0; f < FM_F; f++) {
        const int idx = __shfl_sync(0xffffffffu, gidx, f);
        const float v = __ldcg(&emb[(long)idx * 32 + lane]);
        const float v2 = v * v;
        p1 += v;
        p2 += v2;
        p3 += v2 * v;
    }

    // Lanes 0..15: order-2 dims. Lanes 16..31: order-3 dims.
    float term;
    if (lane < 16) {
        term = 0.5f * (p1 * p1 - p2);
    } else {
        term = (p1 * p1 * p1 - 3.0f * p1 * p2 + 2.0f * p3) * (1.0f / 6.0f);
    }
    term += linv;  // lanes 0..19 contribute linear part, others added 0

    // Warp-wide sum.
    #pragma unroll
    for (int o = 16; o > 0; o >>= 1)
        term += __shfl_xor_sync(0xffffffffu, term, o);

    // Streaming store: output has zero reuse; keep it out of L2's way.
    if (lane == 0)
        __stcs(&out[warp], term + __ldg(&bias[0]));
}

extern "C" void kernel_launch(void* const* d_in, const int* in_sizes, int n_in,
                              void* d_out, int out_size)
{
    const int*   x    = (const int*)d_in[0];
    const float* emb  = (const float*)d_in[1];
    const float* lin  = (const float*)d_in[2];
    const float* bias = (const float*)d_in[3];
    float*       out  = (float*)d_out;

    // 16384 samples, 1 warp each, 8 warps/block -> 2048 blocks (exact grid).
    const int threads = 256;
    const int blocks  = (FM_BATCH * 32) / threads;
    fm_ho_kernel<<<blocks, threads>>>(x, emb, lin, bias, out);
}